// round 7
// baseline (speedup 1.0000x reference)
#include <cuda_runtime.h>
#include <cstdint>
#include <cstddef>

#define T_STEPS 2048
#define NB      32
#define HDIM    256
#define G4H     1024
#define CLUSTER_SZ 8

// ---------------------------------------------------------------------------
// Scratch (device globals — no allocation allowed in kernel_launch)
// ---------------------------------------------------------------------------
__device__ float g_xw0[(size_t)NB * T_STEPS * G4H];    // 268 MB
__device__ float g_h0seq[(size_t)NB * T_STEPS * HDIM]; // 64 MB
__device__ float g_xw1[(size_t)NB * T_STEPS * G4H];    // 268 MB
__device__ float g_h1T[NB * HDIM];

// ---------------------------------------------------------------------------
// Packed fp32x2 helpers (Blackwell FFMA2 path — ptxas won't auto-fuse)
// ---------------------------------------------------------------------------
__device__ __forceinline__ uint64_t fma_x2(uint64_t a, uint64_t b, uint64_t c) {
    uint64_t d;
    asm("fma.rn.f32x2 %0, %1, %2, %3;" : "=l"(d) : "l"(a), "l"(b), "l"(c));
    return d;
}
__device__ __forceinline__ uint64_t pack2(float x, float y) {
    uint64_t d;
    asm("mov.b64 %0, {%1, %2};" : "=l"(d) : "f"(x), "f"(y));
    return d;
}
__device__ __forceinline__ void unpack2(uint64_t v, float& lo, float& hi) {
    asm("mov.b64 {%0, %1}, %2;" : "=f"(lo), "=f"(hi) : "l"(v));
}
__device__ __forceinline__ void lds_v2u64(uint64_t& a, uint64_t& b, uint32_t addr) {
    asm volatile("ld.shared.v2.u64 {%0, %1}, [%2];" : "=l"(a), "=l"(b) : "r"(addr));
}

#define MBARRIER_INIT(addr, count) \
    asm volatile("mbarrier.init.shared.b64 [%0], %1;" \
                 :: "r"((uint32_t)(addr)), "r"((uint32_t)(count)) : "memory")

// Acquire at CLUSTER scope: pairs with producers' cluster-scope release
// arrives; orders our subsequent reads of the peer-written local hbuf.
#define MBARRIER_WAIT_PARITY_CL(mbar_smem_addr, phase_parity) do { \
    uint32_t _mbar = (uint32_t)(mbar_smem_addr); \
    uint32_t _parity = (uint32_t)(phase_parity); \
    uint32_t _done; \
    asm volatile( \
        "{\n\t" \
        ".reg .pred p;\n\t" \
        "mbarrier.try_wait.parity.acquire.cluster.shared::cta.b64 p, [%1], %2;\n\t" \
        "selp.b32 %0, 1, 0, p;\n\t" \
        "}" \
        : "=r"(_done) : "r"(_mbar), "r"(_parity) : "memory"); \
    if (!_done) { \
        asm volatile( \
            "{\n\t" \
            ".reg .pred P1;\n\t" \
            "WAIT_LOOP_%=:\n\t" \
            "mbarrier.try_wait.parity.acquire.cluster.shared::cta.b64 P1, [%0], %1, 0x989680;\n\t" \
            "@P1 bra.uni WAIT_DONE_%=;\n\t" \
            "bra.uni WAIT_LOOP_%=;\n\t" \
            "WAIT_DONE_%=:\n\t" \
            "}" \
            :: "r"(_mbar), "r"(_parity) : "memory"); \
    } \
} while(0)

#define CLUSTER_SYNC() do { \
    asm volatile("barrier.cluster.arrive.aligned;" ::: "memory"); \
    asm volatile("barrier.cluster.wait.aligned;"   ::: "memory"); \
} while (0)

// ---------------------------------------------------------------------------
// GEMM: out[M x 1024] = A[M x K] @ W[K x 1024] + bias   (M = 65536)
// ---------------------------------------------------------------------------
template <int K>
__global__ __launch_bounds__(256)
void gemm_xw(const float* __restrict__ A, const float* __restrict__ W,
             const float* __restrict__ bias, float* __restrict__ out) {
    extern __shared__ float sm[];
    float* a_s = sm;               // [128][65] transposed A tile
    float* w_s = sm + 128 * 65;    // [128][64]

    const int tid = threadIdx.x;
    const long m0 = (long)blockIdx.x * 64;
    const int  n0 = blockIdx.y * 64;

    const int tn = (tid & 15) << 2;
    const int tm = (tid >> 4) << 2;

    const uint32_t ws_b = (uint32_t)__cvta_generic_to_shared(w_s);

    uint64_t acc01[4], acc23[4];
#pragma unroll
    for (int i = 0; i < 4; i++) { acc01[i] = 0ull; acc23[i] = 0ull; }

    for (int k0 = 0; k0 < K; k0 += 128) {
        for (int idx = tid; idx < 64 * 128; idx += 256) {
            int r = idx >> 7;
            int k = idx & 127;
            a_s[k * 65 + r] = A[(m0 + r) * K + k0 + k];
        }
        for (int idx = tid; idx < 128 * 16; idx += 256) {
            int k = idx >> 4, c4 = idx & 15;
            *reinterpret_cast<float4*>(w_s + k * 64 + c4 * 4) =
                *reinterpret_cast<const float4*>(W + (size_t)(k0 + k) * G4H + n0 + c4 * 4);
        }
        __syncthreads();

#pragma unroll 8
        for (int k = 0; k < 128; k++) {
            const float* ap = a_s + k * 65 + tm;
            float a0 = ap[0], a1 = ap[1], a2 = ap[2], a3 = ap[3];
            uint64_t b01, b23;
            lds_v2u64(b01, b23, ws_b + (uint32_t)(k * 64 + tn) * 4u);
            uint64_t aa;
            aa = pack2(a0, a0);
            acc01[0] = fma_x2(aa, b01, acc01[0]); acc23[0] = fma_x2(aa, b23, acc23[0]);
            aa = pack2(a1, a1);
            acc01[1] = fma_x2(aa, b01, acc01[1]); acc23[1] = fma_x2(aa, b23, acc23[1]);
            aa = pack2(a2, a2);
            acc01[2] = fma_x2(aa, b01, acc01[2]); acc23[2] = fma_x2(aa, b23, acc23[2]);
            aa = pack2(a3, a3);
            acc01[3] = fma_x2(aa, b01, acc01[3]); acc23[3] = fma_x2(aa, b23, acc23[3]);
        }
        __syncthreads();
    }

    float4 bv = *reinterpret_cast<const float4*>(bias + n0 + tn);
#pragma unroll
    for (int i = 0; i < 4; i++) {
        float4 o;
        unpack2(acc01[i], o.x, o.y);
        unpack2(acc23[i], o.z, o.w);
        o.x += bv.x; o.y += bv.y; o.z += bv.z; o.w += bv.w;
        *reinterpret_cast<float4*>(out + (m0 + tm + i) * G4H + n0 + tn) = o;
    }
}

// ---------------------------------------------------------------------------
// LSTM recurrence — PUSH with per-peer single-thread bulk copy.
// R4's push topology (one fabric crossing on the critical path) but each
// consumer mbar now receives 8 arrives/step instead of 512 same-address
// atomics (R4's hidden serializer):
//   combine threads -> local 64-float stage -> bar.sync(64) [local drain] ->
//   threads 0..7: thread r bulk-copies the 256B stage to peer r (16 x
//   st.shared::cluster.v4) then ONE release-arrive on peer r's mbar.
// Same-thread store->arrive ordering is architecturally guaranteed — no
// cluster fence (R5's mistake), no pull round (R6's mistake).
// WAR safety transitive as in R4: a peer's arrive for h(t) follows its
// __syncthreads after its dot reads of h(t-1).
// ---------------------------------------------------------------------------
__device__ __forceinline__ float sigmoidf_(float x) {
    return __fdividef(1.f, 1.f + __expf(-x));
}

#define WS_FLOATS   (128 * HDIM)                  // 32768 floats = 128 KB
#define HBUF_OFF    WS_FLOATS                     // [2 parity][2 batch][256]
#define STAGE_OFF   (HBUF_OFF + 2 * 2 * HDIM)     // [2 parity][64]
#define PART_OFF    (STAGE_OFF + 128)             // [2 half][4 gate][2 b][32]
#define MBAR_OFF    (PART_OFF + 512)              // 2 x u64 (8B aligned)
#define REC_FLOATS  (MBAR_OFF + 8)

template <bool STORE_SEQ>
__global__ __launch_bounds__(256, 1) __cluster_dims__(CLUSTER_SZ, 1, 1)
void lstm_rec(const float* __restrict__ xw, const float* __restrict__ U,
              float* __restrict__ out_seq, float* __restrict__ out_last) {
    extern __shared__ float sm[];
    float* w_s  = sm;
    float* hbuf = sm + HBUF_OFF;
    float* part = sm + PART_OFF;

    const int tid  = threadIdx.x;       // 256
    const int half = tid >> 7;          // k-half
    const int g    = (tid >> 5) & 3;    // gate 0..3 (i,f,g,o)
    const int u    = tid & 31;          // unit within CTA slice

    uint32_t rank;
    asm("mov.u32 %0, %%cluster_ctarank;" : "=r"(rank));
    const int cid = blockIdx.x >> 3;
    const int u0  = (int)rank * 32;
    const int b0  = cid * 2;

    const uint32_t smem_b = (uint32_t)__cvta_generic_to_shared(sm);
    const uint32_t mbar_b = smem_b + MBAR_OFF * 4u;
    const uint32_t hbuf_b = smem_b + HBUF_OFF * 4u;
    const uint32_t stage_b = smem_b + STAGE_OFF * 4u;

    if (tid == 0) {
        MBARRIER_INIT(mbar_b,      CLUSTER_SZ);   // parity buffer 0
        MBARRIER_INIT(mbar_b + 8,  CLUSTER_SZ);   // parity buffer 1
    }

    // Load U slice into swizzled SMEM layout:
    //   (k, c) -> float idx ((c>>5)*64 + (k>>2))*128 + (c&31)*4 + (k&3)
    for (int idx = tid; idx < 128 * HDIM; idx += 256) {
        int k = idx >> 7;          // 0..255
        int c = idx & 127;         // gate*32 + unit
        int col = (c >> 5) * HDIM + u0 + (c & 31);
        w_s[(((c >> 5) * 64 + (k >> 2)) << 7) + ((c & 31) << 2) + (k & 3)] =
            U[(size_t)k * G4H + col];
    }
    // Zero h double-buffer + stage + part
    for (int idx = tid; idx < 2 * 2 * HDIM + 128 + 512; idx += 256)
        hbuf[idx] = 0.f;
    __syncthreads();

    // Combine-thread state (warps 0/1)
    const bool is_comb = (tid < 64);
    const int  cb  = tid >> 5;          // batch within pair
    const int  cu  = tid & 31;          // unit
    float cst = 0.f;
    float xwr0 = 0.f, xwr1 = 0.f, xwr2 = 0.f, xwr3 = 0.f;
    const size_t xbase = (size_t)(b0 + cb) * T_STEPS * G4H + u0 + cu;
    uint32_t ra_peer = 0;               // peer base for copy duty (tid<8)
    if (is_comb) {
        xwr0 = xw[xbase + 0 * HDIM];
        xwr1 = xw[xbase + 1 * HDIM];
        xwr2 = xw[xbase + 2 * HDIM];
        xwr3 = xw[xbase + 3 * HDIM];
        if (tid < CLUSTER_SZ) {
            asm volatile("mapa.shared::cluster.u32 %0, %1, %2;"
                         : "=r"(ra_peer) : "r"(smem_b), "r"(tid));
        }
    }

    // mbarriers + zeroed hbuf must be cluster-visible before any peer store.
    CLUSTER_SYNC();

    const uint32_t w_b = smem_b + (uint32_t)g * 32768u +
                         (uint32_t)half * 16384u + (uint32_t)u * 16u;

    int ph0 = 0, ph1 = 0;

    for (int t = 0; t < T_STEPS; t++) {
        // Wait for h(t-1): stored at parity (t-1)&1, signaled on mbar[(t-1)&1]
        if (t > 0) {
            if (t & 1) { MBARRIER_WAIT_PARITY_CL(mbar_b,     ph0); ph0 ^= 1; }
            else       { MBARRIER_WAIT_PARITY_CL(mbar_b + 8, ph1); ph1 ^= 1; }
        }

        const int rd = (t + 1) & 1;     // parity holding h(t-1)
        const uint32_t h0_b = hbuf_b + (uint32_t)(rd * 2 * HDIM + half * 128) * 4u;
        const uint32_t h1_b = h0_b + HDIM * 4u;

        uint64_t a01 = 0ull, a23 = 0ull, c01 = 0ull, c23 = 0ull;
#pragma unroll
        for (int k4 = 0; k4 < 32; k4++) {
            uint64_t w01, w23, p01, p23, q01, q23;
            lds_v2u64(w01, w23, w_b + (uint32_t)k4 * 512u);  // conflict-free
            lds_v2u64(p01, p23, h0_b + (uint32_t)k4 * 16u);  // broadcast
            lds_v2u64(q01, q23, h1_b + (uint32_t)k4 * 16u);  // broadcast
            a01 = fma_x2(w01, p01, a01);
            a23 = fma_x2(w23, p23, a23);
            c01 = fma_x2(w01, q01, c01);
            c23 = fma_x2(w23, q23, c23);
        }
        float s0, s1, s2, s3, r0, r1, r2, r3;
        unpack2(a01, s0, s1); unpack2(a23, s2, s3);
        unpack2(c01, r0, r1); unpack2(c23, r2, r3);
        float pa = (s0 + s1) + (s2 + s3);
        float pb = (r0 + r1) + (r2 + r3);

        // part[half][gate][batch][unit]
        part[((half * 4 + g) * 2 + 0) * 32 + u] = pa;
        part[((half * 4 + g) * 2 + 1) * 32 + u] = pb;
        __syncthreads();

        if (is_comb) {
            float zi = xwr0 + part[(0 * 2 + cb) * 32 + cu]
                            + part[((4 + 0) * 2 + cb) * 32 + cu];
            float zf = xwr1 + part[(1 * 2 + cb) * 32 + cu]
                            + part[((4 + 1) * 2 + cb) * 32 + cu];
            float zg = xwr2 + part[(2 * 2 + cb) * 32 + cu]
                            + part[((4 + 2) * 2 + cb) * 32 + cu];
            float zo = xwr3 + part[(3 * 2 + cb) * 32 + cu]
                            + part[((4 + 3) * 2 + cb) * 32 + cu];

            float iv = sigmoidf_(zi);
            float fv = sigmoidf_(zf);
            float ov = sigmoidf_(zo);
            cst = fmaf(fv, cst, iv * zg);  // linear candidate activation
            float h = ov * cst;            // linear output activation

            if (t + 1 < T_STEPS) {
                // Local stage write (parity t&1); cheap local drain; then
                // 8 copy threads: 256B bulk push + single arrive per peer.
                const uint32_t st_addr = stage_b +
                    (uint32_t)((t & 1) * 64 + cb * 32 + cu) * 4u;
                asm volatile("st.shared.f32 [%0], %1;"
                             :: "r"(st_addr), "f"(h) : "memory");
                asm volatile("bar.sync 1, 64;" ::: "memory");

                if (tid < CLUSTER_SZ) {
                    const uint32_t src0 = stage_b + (uint32_t)((t & 1) * 64) * 4u;
                    const uint32_t dst0 = ra_peer + HBUF_OFF * 4u +
                        (uint32_t)((t & 1) * 2 * HDIM + u0) * 4u;
#pragma unroll
                    for (int j = 0; j < 16; j++) {
                        const int bb = j >> 3, jj = j & 7;
                        float4 v;
                        asm volatile("ld.shared.v4.f32 {%0,%1,%2,%3}, [%4];"
                                     : "=f"(v.x), "=f"(v.y), "=f"(v.z), "=f"(v.w)
                                     : "r"(src0 + (uint32_t)(bb * 32 + jj * 4) * 4u));
                        asm volatile("st.shared::cluster.v4.f32 [%0], {%1,%2,%3,%4};"
                                     :: "r"(dst0 + (uint32_t)(bb * HDIM + jj * 4) * 4u),
                                        "f"(v.x), "f"(v.y), "f"(v.z), "f"(v.w)
                                     : "memory");
                    }
                    // Same-thread release-arrive: orders this thread's stores.
                    asm volatile("mbarrier.arrive.release.cluster.shared::cluster.b64 _, [%0];"
                                 :: "r"(ra_peer + MBAR_OFF * 4u + ((uint32_t)(t & 1) << 3))
                                 : "memory");
                }
            }

            if (STORE_SEQ) {
                out_seq[((size_t)(b0 + cb) * T_STEPS + t) * HDIM + u0 + cu] = h;
            } else if (t == T_STEPS - 1) {
                out_last[(b0 + cb) * HDIM + u0 + cu] = h;
            }

            // prefetch next step's xw (after the signal is on the wire)
            if (t + 1 < T_STEPS) {
                const size_t xb = xbase + (size_t)(t + 1) * G4H;
                xwr0 = xw[xb + 0 * HDIM];
                xwr1 = xw[xb + 1 * HDIM];
                xwr2 = xw[xb + 2 * HDIM];
                xwr3 = xw[xb + 3 * HDIM];
            }
        }
        // No end-of-step barrier: next-step hbuf/part/stage writes are
        // ordered behind the mbar wait (requires this CTA's prior arrive).
    }
}

// ---------------------------------------------------------------------------
// Final FC: out[32,1,128] = h1T[32,256] @ Wfc[256,128] + bfc
// ---------------------------------------------------------------------------
__global__ __launch_bounds__(128)
void fc_kernel(const float* __restrict__ h, const float* __restrict__ Wfc,
               const float* __restrict__ bfc, float* __restrict__ out) {
    const int b = blockIdx.x;
    const int j = threadIdx.x;
    const float* hb = h + b * HDIM;
    float acc = bfc[j];
#pragma unroll 16
    for (int k = 0; k < HDIM; k++)
        acc = fmaf(hb[k], Wfc[k * 128 + j], acc);
    out[b * 128 + j] = acc;
}

// ---------------------------------------------------------------------------
// Launch
// ---------------------------------------------------------------------------
#define GEMM_SMEM ((128 * 65 + 128 * 64) * 4)   // 66048
#define REC_SMEM  (REC_FLOATS * 4)              // ~138 KB

extern "C" void kernel_launch(void* const* d_in, const int* in_sizes, int n_in,
                              void* d_out, int out_size) {
    const float* x   = (const float*)d_in[0];
    const float* W0  = (const float*)d_in[1];
    const float* U0  = (const float*)d_in[2];
    const float* b0v = (const float*)d_in[3];
    const float* W1  = (const float*)d_in[4];
    const float* U1  = (const float*)d_in[5];
    const float* b1v = (const float*)d_in[6];
    const float* Wfc = (const float*)d_in[7];
    const float* bfc = (const float*)d_in[8];
    float* out = (float*)d_out;

    float *xw0, *h0seq, *xw1, *h1T;
    cudaGetSymbolAddress((void**)&xw0,   g_xw0);
    cudaGetSymbolAddress((void**)&h0seq, g_h0seq);
    cudaGetSymbolAddress((void**)&xw1,   g_xw1);
    cudaGetSymbolAddress((void**)&h1T,   g_h1T);

    cudaFuncSetAttribute(gemm_xw<128>, cudaFuncAttributeMaxDynamicSharedMemorySize, GEMM_SMEM);
    cudaFuncSetAttribute(gemm_xw<256>, cudaFuncAttributeMaxDynamicSharedMemorySize, GEMM_SMEM);
    cudaFuncSetAttribute(lstm_rec<true>,  cudaFuncAttributeMaxDynamicSharedMemorySize, REC_SMEM);
    cudaFuncSetAttribute(lstm_rec<false>, cudaFuncAttributeMaxDynamicSharedMemorySize, REC_SMEM);

    const long M = (long)NB * T_STEPS;  // 65536 rows

    gemm_xw<128><<<dim3((unsigned)(M / 64), G4H / 64), 256, GEMM_SMEM>>>(x, W0, b0v, xw0);
    lstm_rec<true><<<NB / 2 * CLUSTER_SZ, 256, REC_SMEM>>>(xw0, U0, h0seq, nullptr);
    gemm_xw<256><<<dim3((unsigned)(M / 64), G4H / 64), 256, GEMM_SMEM>>>(h0seq, W1, b1v, xw1);
    lstm_rec<false><<<NB / 2 * CLUSTER_SZ, 256, REC_SMEM>>>(xw1, U1, nullptr, h1T);
    fc_kernel<<<NB, 128>>>(h1T, Wfc, bfc, out);
}

// round 9
// speedup vs baseline: 2.0922x; 2.0922x over previous
#include <cuda_runtime.h>
#include <cstdint>
#include <cstddef>

#define T_STEPS 2048
#define NB      32
#define HDIM    256
#define G4H     1024
#define CLUSTER_SZ 8

// ---------------------------------------------------------------------------
// Scratch (device globals — no allocation allowed in kernel_launch)
// ---------------------------------------------------------------------------
__device__ float g_xw0[(size_t)NB * T_STEPS * G4H];    // 268 MB
__device__ float g_h0seq[(size_t)NB * T_STEPS * HDIM]; // 64 MB
__device__ float g_xw1[(size_t)NB * T_STEPS * G4H];    // 268 MB
__device__ float g_h1T[NB * HDIM];

// ---------------------------------------------------------------------------
// Packed fp32x2 helpers (Blackwell FFMA2 path — ptxas won't auto-fuse)
// ---------------------------------------------------------------------------
__device__ __forceinline__ uint64_t fma_x2(uint64_t a, uint64_t b, uint64_t c) {
    uint64_t d;
    asm("fma.rn.f32x2 %0, %1, %2, %3;" : "=l"(d) : "l"(a), "l"(b), "l"(c));
    return d;
}
__device__ __forceinline__ uint64_t pack2(float x, float y) {
    uint64_t d;
    asm("mov.b64 %0, {%1, %2};" : "=l"(d) : "f"(x), "f"(y));
    return d;
}
__device__ __forceinline__ void unpack2(uint64_t v, float& lo, float& hi) {
    asm("mov.b64 {%0, %1}, %2;" : "=f"(lo), "=f"(hi) : "l"(v));
}
__device__ __forceinline__ void lds_v2u64(uint64_t& a, uint64_t& b, uint32_t addr) {
    asm volatile("ld.shared.v2.u64 {%0, %1}, [%2];" : "=l"(a), "=l"(b) : "r"(addr));
}

#define MBARRIER_INIT(addr, count) \
    asm volatile("mbarrier.init.shared.b64 [%0], %1;" \
                 :: "r"((uint32_t)(addr)), "r"((uint32_t)(count)) : "memory")

#define MBARRIER_WAIT_PARITY(mbar_smem_addr, phase_parity) do { \
    uint32_t _mbar = (uint32_t)(mbar_smem_addr); \
    uint32_t _parity = (uint32_t)(phase_parity); \
    uint32_t _done; \
    asm volatile( \
        "{\n\t" \
        ".reg .pred p;\n\t" \
        "mbarrier.try_wait.parity.acquire.cta.shared::cta.b64 p, [%1], %2;\n\t" \
        "selp.b32 %0, 1, 0, p;\n\t" \
        "}" \
        : "=r"(_done) : "r"(_mbar), "r"(_parity) : "memory"); \
    if (!_done) { \
        asm volatile( \
            "{\n\t" \
            ".reg .pred P1;\n\t" \
            "WAIT_LOOP_%=:\n\t" \
            "mbarrier.try_wait.parity.acquire.cta.shared::cta.b64 P1, [%0], %1, 0x989680;\n\t" \
            "@P1 bra.uni WAIT_DONE_%=;\n\t" \
            "bra.uni WAIT_LOOP_%=;\n\t" \
            "WAIT_DONE_%=:\n\t" \
            "}" \
            :: "r"(_mbar), "r"(_parity) : "memory"); \
    } \
} while(0)

#define CLUSTER_SYNC() do { \
    asm volatile("barrier.cluster.arrive.aligned;" ::: "memory"); \
    asm volatile("barrier.cluster.wait.aligned;"   ::: "memory"); \
} while (0)

// ---------------------------------------------------------------------------
// GEMM: out[M x 1024] = A[M x K] @ W[K x 1024] + bias   (M = 65536)
// ---------------------------------------------------------------------------
template <int K>
__global__ __launch_bounds__(256)
void gemm_xw(const float* __restrict__ A, const float* __restrict__ W,
             const float* __restrict__ bias, float* __restrict__ out) {
    extern __shared__ float sm[];
    float* a_s = sm;               // [128][65] transposed A tile
    float* w_s = sm + 128 * 65;    // [128][64]

    const int tid = threadIdx.x;
    const long m0 = (long)blockIdx.x * 64;
    const int  n0 = blockIdx.y * 64;

    const int tn = (tid & 15) << 2;
    const int tm = (tid >> 4) << 2;

    const uint32_t ws_b = (uint32_t)__cvta_generic_to_shared(w_s);

    uint64_t acc01[4], acc23[4];
#pragma unroll
    for (int i = 0; i < 4; i++) { acc01[i] = 0ull; acc23[i] = 0ull; }

    for (int k0 = 0; k0 < K; k0 += 128) {
        for (int idx = tid; idx < 64 * 128; idx += 256) {
            int r = idx >> 7;
            int k = idx & 127;
            a_s[k * 65 + r] = A[(m0 + r) * K + k0 + k];
        }
        for (int idx = tid; idx < 128 * 16; idx += 256) {
            int k = idx >> 4, c4 = idx & 15;
            *reinterpret_cast<float4*>(w_s + k * 64 + c4 * 4) =
                *reinterpret_cast<const float4*>(W + (size_t)(k0 + k) * G4H + n0 + c4 * 4);
        }
        __syncthreads();

#pragma unroll 8
        for (int k = 0; k < 128; k++) {
            const float* ap = a_s + k * 65 + tm;
            float a0 = ap[0], a1 = ap[1], a2 = ap[2], a3 = ap[3];
            uint64_t b01, b23;
            lds_v2u64(b01, b23, ws_b + (uint32_t)(k * 64 + tn) * 4u);
            uint64_t aa;
            aa = pack2(a0, a0);
            acc01[0] = fma_x2(aa, b01, acc01[0]); acc23[0] = fma_x2(aa, b23, acc23[0]);
            aa = pack2(a1, a1);
            acc01[1] = fma_x2(aa, b01, acc01[1]); acc23[1] = fma_x2(aa, b23, acc23[1]);
            aa = pack2(a2, a2);
            acc01[2] = fma_x2(aa, b01, acc01[2]); acc23[2] = fma_x2(aa, b23, acc23[2]);
            aa = pack2(a3, a3);
            acc01[3] = fma_x2(aa, b01, acc01[3]); acc23[3] = fma_x2(aa, b23, acc23[3]);
        }
        __syncthreads();
    }

    float4 bv = *reinterpret_cast<const float4*>(bias + n0 + tn);
#pragma unroll
    for (int i = 0; i < 4; i++) {
        float4 o;
        unpack2(acc01[i], o.x, o.y);
        unpack2(acc23[i], o.z, o.w);
        o.x += bv.x; o.y += bv.y; o.z += bv.z; o.w += bv.w;
        *reinterpret_cast<float4*>(out + (m0 + tm + i) * G4H + n0 + tn) = o;
    }
}

// ---------------------------------------------------------------------------
// LSTM recurrence — R4 push/signal structure (measured best), dot engine in
// REGISTERS. Thread (khalf, g, u) holds its 128 U weights as 64 packed f32x2
// regs (loaded once, coalesced). Per step: 64 broadcast LDS.128 of h
// (1 crossbar phase each) + 128 FFMA2, zero w-side LDS.
// Signaling identical to R4: per combine-thread remote st.shared::cluster +
// remote mbarrier arrives (count 512). No bar.sync / fence / pull (R5-R7
// each measured those as regressions).
// ---------------------------------------------------------------------------
__device__ __forceinline__ float sigmoidf_(float x) {
    return __fdividef(1.f, 1.f + __expf(-x));
}

#define HBUF_OFF    0                             // [2 parity][2 batch][256]
#define PART_OFF    (2 * 2 * HDIM)                // [2 khalf][4 gate][2 b][32]
#define MBAR_OFF    (PART_OFF + 512)              // 2 x u64 (8B aligned)
#define REC_FLOATS  (MBAR_OFF + 8)

template <bool STORE_SEQ>
__global__ __launch_bounds__(256, 1) __cluster_dims__(CLUSTER_SZ, 1, 1)
void lstm_rec(const float* __restrict__ xw, const float* __restrict__ U,
              float* __restrict__ out_seq, float* __restrict__ out_last) {
    extern __shared__ float sm[];
    float* hbuf = sm + HBUF_OFF;
    float* part = sm + PART_OFF;

    const int tid   = threadIdx.x;      // 256
    const int khalf = tid >> 7;         // k-half (0: k<128, 1: k>=128)
    const int g     = (tid >> 5) & 3;   // gate 0..3 (i,f,g,o)
    const int u     = tid & 31;         // unit within CTA slice

    uint32_t rank;
    asm("mov.u32 %0, %%cluster_ctarank;" : "=r"(rank));
    const int cid = blockIdx.x >> 3;
    const int u0  = (int)rank * 32;
    const int b0  = cid * 2;

    const uint32_t smem_b = (uint32_t)__cvta_generic_to_shared(sm);
    const uint32_t mbar_b = smem_b + MBAR_OFF * 4u;
    const uint32_t hbuf_b = smem_b + HBUF_OFF * 4u;

    if (tid == 0) {
        MBARRIER_INIT(mbar_b,      512);   // parity buffer 0
        MBARRIER_INIT(mbar_b + 8,  512);   // parity buffer 1
    }

    // ---- This thread's 128 U weights -> 64 packed f32x2 registers.
    // gcol consecutive across lanes -> coalesced 128B lines per k row.
    const int gcol = g * HDIM + u0 + u;
    uint64_t wreg[64];
    {
        const float* Up = U + (size_t)(khalf * 128) * G4H + gcol;
#pragma unroll
        for (int k4 = 0; k4 < 32; k4++) {
            float w0 = Up[(k4 * 4 + 0) * G4H];
            float w1 = Up[(k4 * 4 + 1) * G4H];
            float w2 = Up[(k4 * 4 + 2) * G4H];
            float w3 = Up[(k4 * 4 + 3) * G4H];
            wreg[k4 * 2 + 0] = pack2(w0, w1);
            wreg[k4 * 2 + 1] = pack2(w2, w3);
        }
    }

    // Zero h double-buffer + partials
    for (int idx = tid; idx < 2 * 2 * HDIM + 512; idx += 256) hbuf[idx] = 0.f;
    __syncthreads();

    // Combine-thread state (warps 0/1)
    const bool is_comb = (tid < 64);
    const int  cb  = tid >> 5;          // batch within pair
    const int  cu  = tid & 31;          // unit
    float cst = 0.f;
    float xwr0 = 0.f, xwr1 = 0.f, xwr2 = 0.f, xwr3 = 0.f;
    const size_t xbase = (size_t)(b0 + cb) * T_STEPS * G4H + u0 + cu;
    uint32_t ra_base[CLUSTER_SZ];       // mapa'd peer SMEM bases (combine only)
    if (is_comb) {
        xwr0 = xw[xbase + 0 * HDIM];
        xwr1 = xw[xbase + 1 * HDIM];
        xwr2 = xw[xbase + 2 * HDIM];
        xwr3 = xw[xbase + 3 * HDIM];
#pragma unroll
        for (int r = 0; r < CLUSTER_SZ; r++) {
            asm volatile("mapa.shared::cluster.u32 %0, %1, %2;"
                         : "=r"(ra_base[r]) : "r"(smem_b), "r"(r));
        }
    }

    // mbarriers + zeroed hbuf must be cluster-visible before any peer store.
    CLUSTER_SYNC();

    int ph0 = 0, ph1 = 0;

    for (int t = 0; t < T_STEPS; t++) {
        // Wait for h(t-1): lives in buf[(t+1)&1], signaled on mbar[(t+1)&1]
        if (t > 0) {
            if (t & 1) { MBARRIER_WAIT_PARITY(mbar_b,     ph0); ph0 ^= 1; }
            else       { MBARRIER_WAIT_PARITY(mbar_b + 8, ph1); ph1 ^= 1; }
        }

        const int rd = (t + 1) & 1;
        const uint32_t h0_b = hbuf_b + (uint32_t)(rd * 2 * HDIM + khalf * 128) * 4u;
        const uint32_t h1_b = h0_b + HDIM * 4u;

        uint64_t a01 = 0ull, a23 = 0ull, c01 = 0ull, c23 = 0ull;
#pragma unroll
        for (int k4 = 0; k4 < 32; k4++) {
            uint64_t p01, p23, q01, q23;
            lds_v2u64(p01, p23, h0_b + (uint32_t)k4 * 16u);  // broadcast
            lds_v2u64(q01, q23, h1_b + (uint32_t)k4 * 16u);  // broadcast
            a01 = fma_x2(wreg[k4 * 2 + 0], p01, a01);
            a23 = fma_x2(wreg[k4 * 2 + 1], p23, a23);
            c01 = fma_x2(wreg[k4 * 2 + 0], q01, c01);
            c23 = fma_x2(wreg[k4 * 2 + 1], q23, c23);
        }
        float s0, s1, s2, s3, r0, r1, r2, r3;
        unpack2(a01, s0, s1); unpack2(a23, s2, s3);
        unpack2(c01, r0, r1); unpack2(c23, r2, r3);
        float pa = (s0 + s1) + (s2 + s3);
        float pb = (r0 + r1) + (r2 + r3);

        // part[khalf][gate][batch][unit]
        part[((khalf * 4 + g) * 2 + 0) * 32 + u] = pa;
        part[((khalf * 4 + g) * 2 + 1) * 32 + u] = pb;
        __syncthreads();

        if (is_comb) {
            float zi = xwr0 + part[(0 * 2 + cb) * 32 + cu]
                            + part[((4 + 0) * 2 + cb) * 32 + cu];
            float zf = xwr1 + part[(1 * 2 + cb) * 32 + cu]
                            + part[((4 + 1) * 2 + cb) * 32 + cu];
            float zg = xwr2 + part[(2 * 2 + cb) * 32 + cu]
                            + part[((4 + 2) * 2 + cb) * 32 + cu];
            float zo = xwr3 + part[(3 * 2 + cb) * 32 + cu]
                            + part[((4 + 3) * 2 + cb) * 32 + cu];

            float iv = sigmoidf_(zi);
            float fv = sigmoidf_(zf);
            float ov = sigmoidf_(zo);
            cst = fmaf(fv, cst, iv * zg);  // linear candidate activation
            float h = ov * cst;            // linear output activation

            if (STORE_SEQ) {
                out_seq[((size_t)(b0 + cb) * T_STEPS + t) * HDIM + u0 + cu] = h;
            } else if (t == T_STEPS - 1) {
                out_last[(b0 + cb) * HDIM + u0 + cu] = h;
            }

            if (t + 1 < T_STEPS) {
                // R4 signaling: push h(t) slice to all 8 peers' buf[t&1],
                // then arrive on each peer's mbar[t&1] (fire-and-forget).
                const uint32_t hoff = HBUF_OFF * 4u +
                    ((uint32_t)((t & 1) * 2 * HDIM + cb * HDIM + u0 + cu) << 2);
#pragma unroll
                for (int r = 0; r < CLUSTER_SZ; r++) {
                    asm volatile("st.shared::cluster.f32 [%0], %1;"
                                 :: "r"(ra_base[r] + hoff), "f"(h) : "memory");
                }
                const uint32_t moff = MBAR_OFF * 4u + ((uint32_t)(t & 1) << 3);
#pragma unroll
                for (int r = 0; r < CLUSTER_SZ; r++) {
                    asm volatile("mbarrier.arrive.shared::cluster.b64 _, [%0];"
                                 :: "r"(ra_base[r] + moff) : "memory");
                }
            }

            // prefetch next step's xw (after the signal is on the wire)
            if (t + 1 < T_STEPS) {
                const size_t xb = xbase + (size_t)(t + 1) * G4H;
                xwr0 = xw[xb + 0 * HDIM];
                xwr1 = xw[xb + 1 * HDIM];
                xwr2 = xw[xb + 2 * HDIM];
                xwr3 = xw[xb + 3 * HDIM];
            }
        }
        // No end-of-step barrier: next-step part/hbuf writes are ordered
        // behind the mbar wait (which requires this CTA's own arrives).
    }
}

// ---------------------------------------------------------------------------
// Final FC: out[32,1,128] = h1T[32,256] @ Wfc[256,128] + bfc
// ---------------------------------------------------------------------------
__global__ __launch_bounds__(128)
void fc_kernel(const float* __restrict__ h, const float* __restrict__ Wfc,
               const float* __restrict__ bfc, float* __restrict__ out) {
    const int b = blockIdx.x;
    const int j = threadIdx.x;
    const float* hb = h + b * HDIM;
    float acc = bfc[j];
#pragma unroll 16
    for (int k = 0; k < HDIM; k++)
        acc = fmaf(hb[k], Wfc[k * 128 + j], acc);
    out[b * 128 + j] = acc;
}

// ---------------------------------------------------------------------------
// Launch
// ---------------------------------------------------------------------------
#define GEMM_SMEM ((128 * 65 + 128 * 64) * 4)   // 66048
#define REC_SMEM  (REC_FLOATS * 4)              // ~6 KB

extern "C" void kernel_launch(void* const* d_in, const int* in_sizes, int n_in,
                              void* d_out, int out_size) {
    const float* x   = (const float*)d_in[0];
    const float* W0  = (const float*)d_in[1];
    const float* U0  = (const float*)d_in[2];
    const float* b0v = (const float*)d_in[3];
    const float* W1  = (const float*)d_in[4];
    const float* U1  = (const float*)d_in[5];
    const float* b1v = (const float*)d_in[6];
    const float* Wfc = (const float*)d_in[7];
    const float* bfc = (const float*)d_in[8];
    float* out = (float*)d_out;

    float *xw0, *h0seq, *xw1, *h1T;
    cudaGetSymbolAddress((void**)&xw0,   g_xw0);
    cudaGetSymbolAddress((void**)&h0seq, g_h0seq);
    cudaGetSymbolAddress((void**)&xw1,   g_xw1);
    cudaGetSymbolAddress((void**)&h1T,   g_h1T);

    cudaFuncSetAttribute(gemm_xw<128>, cudaFuncAttributeMaxDynamicSharedMemorySize, GEMM_SMEM);
    cudaFuncSetAttribute(gemm_xw<256>, cudaFuncAttributeMaxDynamicSharedMemorySize, GEMM_SMEM);
    cudaFuncSetAttribute(lstm_rec<true>,  cudaFuncAttributeMaxDynamicSharedMemorySize, REC_SMEM);
    cudaFuncSetAttribute(lstm_rec<false>, cudaFuncAttributeMaxDynamicSharedMemorySize, REC_SMEM);

    const long M = (long)NB * T_STEPS;  // 65536 rows

    gemm_xw<128><<<dim3((unsigned)(M / 64), G4H / 64), 256, GEMM_SMEM>>>(x, W0, b0v, xw0);
    lstm_rec<true><<<NB / 2 * CLUSTER_SZ, 256, REC_SMEM>>>(xw0, U0, h0seq, nullptr);
    gemm_xw<256><<<dim3((unsigned)(M / 64), G4H / 64), 256, GEMM_SMEM>>>(h0seq, W1, b1v, xw1);
    lstm_rec<false><<<NB / 2 * CLUSTER_SZ, 256, REC_SMEM>>>(xw1, U1, nullptr, h1T);
    fc_kernel<<<NB, 128>>>(h1T, Wfc, bfc, out);
}

// round 10
// speedup vs baseline: 2.1604x; 1.0326x over previous
#include <cuda_runtime.h>
#include <cstdint>
#include <cstddef>

#define T_STEPS 2048
#define NB      32
#define HDIM    256
#define G4H     1024
#define CLUSTER_SZ 8

// ---------------------------------------------------------------------------
// Scratch (device globals — no allocation allowed in kernel_launch)
// ---------------------------------------------------------------------------
__device__ float g_xw0[(size_t)NB * T_STEPS * G4H];    // 268 MB
__device__ float g_h0seq[(size_t)NB * T_STEPS * HDIM]; // 64 MB
__device__ float g_xw1[(size_t)NB * T_STEPS * G4H];    // 268 MB
__device__ float g_h1T[NB * HDIM];

// ---------------------------------------------------------------------------
// Packed fp32x2 helpers (Blackwell FFMA2 path — ptxas won't auto-fuse)
// ---------------------------------------------------------------------------
__device__ __forceinline__ uint64_t fma_x2(uint64_t a, uint64_t b, uint64_t c) {
    uint64_t d;
    asm("fma.rn.f32x2 %0, %1, %2, %3;" : "=l"(d) : "l"(a), "l"(b), "l"(c));
    return d;
}
__device__ __forceinline__ uint64_t pack2(float x, float y) {
    uint64_t d;
    asm("mov.b64 %0, {%1, %2};" : "=l"(d) : "f"(x), "f"(y));
    return d;
}
__device__ __forceinline__ void unpack2(uint64_t v, float& lo, float& hi) {
    asm("mov.b64 {%0, %1}, %2;" : "=f"(lo), "=f"(hi) : "l"(v));
}
__device__ __forceinline__ void lds_v2u64(uint64_t& a, uint64_t& b, uint32_t addr) {
    asm volatile("ld.shared.v2.u64 {%0, %1}, [%2];" : "=l"(a), "=l"(b) : "r"(addr));
}

#define MBARRIER_INIT(addr, count) \
    asm volatile("mbarrier.init.shared.b64 [%0], %1;" \
                 :: "r"((uint32_t)(addr)), "r"((uint32_t)(count)) : "memory")

#define MBARRIER_WAIT_PARITY(mbar_smem_addr, phase_parity) do { \
    uint32_t _mbar = (uint32_t)(mbar_smem_addr); \
    uint32_t _parity = (uint32_t)(phase_parity); \
    uint32_t _done; \
    asm volatile( \
        "{\n\t" \
        ".reg .pred p;\n\t" \
        "mbarrier.try_wait.parity.acquire.cta.shared::cta.b64 p, [%1], %2;\n\t" \
        "selp.b32 %0, 1, 0, p;\n\t" \
        "}" \
        : "=r"(_done) : "r"(_mbar), "r"(_parity) : "memory"); \
    if (!_done) { \
        asm volatile( \
            "{\n\t" \
            ".reg .pred P1;\n\t" \
            "WAIT_LOOP_%=:\n\t" \
            "mbarrier.try_wait.parity.acquire.cta.shared::cta.b64 P1, [%0], %1, 0x989680;\n\t" \
            "@P1 bra.uni WAIT_DONE_%=;\n\t" \
            "bra.uni WAIT_LOOP_%=;\n\t" \
            "WAIT_DONE_%=:\n\t" \
            "}" \
            :: "r"(_mbar), "r"(_parity) : "memory"); \
    } \
} while(0)

#define CLUSTER_SYNC() do { \
    asm volatile("barrier.cluster.arrive.aligned;" ::: "memory"); \
    asm volatile("barrier.cluster.wait.aligned;"   ::: "memory"); \
} while (0)

// ---------------------------------------------------------------------------
// GEMM: out[M x 1024] = A[M x K] @ W[K x 1024] + bias   (M = 65536)
// ---------------------------------------------------------------------------
template <int K>
__global__ __launch_bounds__(256)
void gemm_xw(const float* __restrict__ A, const float* __restrict__ W,
             const float* __restrict__ bias, float* __restrict__ out) {
    extern __shared__ float sm[];
    float* a_s = sm;               // [128][65] transposed A tile
    float* w_s = sm + 128 * 65;    // [128][64]

    const int tid = threadIdx.x;
    const long m0 = (long)blockIdx.x * 64;
    const int  n0 = blockIdx.y * 64;

    const int tn = (tid & 15) << 2;
    const int tm = (tid >> 4) << 2;

    const uint32_t ws_b = (uint32_t)__cvta_generic_to_shared(w_s);

    uint64_t acc01[4], acc23[4];
#pragma unroll
    for (int i = 0; i < 4; i++) { acc01[i] = 0ull; acc23[i] = 0ull; }

    for (int k0 = 0; k0 < K; k0 += 128) {
        for (int idx = tid; idx < 64 * 128; idx += 256) {
            int r = idx >> 7;
            int k = idx & 127;
            a_s[k * 65 + r] = A[(m0 + r) * K + k0 + k];
        }
        for (int idx = tid; idx < 128 * 16; idx += 256) {
            int k = idx >> 4, c4 = idx & 15;
            *reinterpret_cast<float4*>(w_s + k * 64 + c4 * 4) =
                *reinterpret_cast<const float4*>(W + (size_t)(k0 + k) * G4H + n0 + c4 * 4);
        }
        __syncthreads();

#pragma unroll 8
        for (int k = 0; k < 128; k++) {
            const float* ap = a_s + k * 65 + tm;
            float a0 = ap[0], a1 = ap[1], a2 = ap[2], a3 = ap[3];
            uint64_t b01, b23;
            lds_v2u64(b01, b23, ws_b + (uint32_t)(k * 64 + tn) * 4u);
            uint64_t aa;
            aa = pack2(a0, a0);
            acc01[0] = fma_x2(aa, b01, acc01[0]); acc23[0] = fma_x2(aa, b23, acc23[0]);
            aa = pack2(a1, a1);
            acc01[1] = fma_x2(aa, b01, acc01[1]); acc23[1] = fma_x2(aa, b23, acc23[1]);
            aa = pack2(a2, a2);
            acc01[2] = fma_x2(aa, b01, acc01[2]); acc23[2] = fma_x2(aa, b23, acc23[2]);
            aa = pack2(a3, a3);
            acc01[3] = fma_x2(aa, b01, acc01[3]); acc23[3] = fma_x2(aa, b23, acc23[3]);
        }
        __syncthreads();
    }

    float4 bv = *reinterpret_cast<const float4*>(bias + n0 + tn);
#pragma unroll
    for (int i = 0; i < 4; i++) {
        float4 o;
        unpack2(acc01[i], o.x, o.y);
        unpack2(acc23[i], o.z, o.w);
        o.x += bv.x; o.y += bv.y; o.z += bv.z; o.w += bv.w;
        *reinterpret_cast<float4*>(out + (m0 + tm + i) * G4H + n0 + tn) = o;
    }
}

// ---------------------------------------------------------------------------
// LSTM recurrence — R4/R9 push/signal structure (measured best), register-
// resident U, now with 512 threads and a 4-way k-split:
// thread (kq, g, u) holds 64 U weights (32 packed f32x2 regs) and computes
// the 2-batch partial dot over k in [kq*64, kq*64+64): 16 iters of
// 2 broadcast LDS.128 + 4 FFMA2. 16 warps (4/SMSP) double latency hiding;
// per-thread dot chain halves vs R9. Combine warps sum 4 partials/gate.
// Signaling identical to R4/R9: per combine-thread remote st.shared::cluster
// + remote mbarrier arrives (count 512); no bar.sync / fence / pull
// (R5-R7 each measured those as regressions).
// ---------------------------------------------------------------------------
__device__ __forceinline__ float sigmoidf_(float x) {
    return __fdividef(1.f, 1.f + __expf(-x));
}

#define HBUF_OFF    0                             // [2 parity][2 batch][256]
#define PART_OFF    (2 * 2 * HDIM)                // [4 kq][4 gate][2 b][32]
#define MBAR_OFF    (PART_OFF + 1024)             // 2 x u64 (8B aligned)
#define REC_FLOATS  (MBAR_OFF + 8)
#define REC_THREADS 512

template <bool STORE_SEQ>
__global__ __launch_bounds__(REC_THREADS, 1) __cluster_dims__(CLUSTER_SZ, 1, 1)
void lstm_rec(const float* __restrict__ xw, const float* __restrict__ U,
              float* __restrict__ out_seq, float* __restrict__ out_last) {
    extern __shared__ float sm[];
    float* hbuf = sm + HBUF_OFF;
    float* part = sm + PART_OFF;

    const int tid = threadIdx.x;        // 512
    const int kq  = tid >> 7;           // k-quarter 0..3
    const int g   = (tid >> 5) & 3;     // gate 0..3 (i,f,g,o)
    const int u   = tid & 31;           // unit within CTA slice

    uint32_t rank;
    asm("mov.u32 %0, %%cluster_ctarank;" : "=r"(rank));
    const int cid = blockIdx.x >> 3;
    const int u0  = (int)rank * 32;
    const int b0  = cid * 2;

    const uint32_t smem_b = (uint32_t)__cvta_generic_to_shared(sm);
    const uint32_t mbar_b = smem_b + MBAR_OFF * 4u;
    const uint32_t hbuf_b = smem_b + HBUF_OFF * 4u;

    if (tid == 0) {
        MBARRIER_INIT(mbar_b,      512);   // parity buffer 0
        MBARRIER_INIT(mbar_b + 8,  512);   // parity buffer 1
    }

    // ---- This thread's 64 U weights -> 32 packed f32x2 registers.
    // gcol consecutive across lanes -> coalesced 128B lines per k row.
    const int gcol = g * HDIM + u0 + u;
    uint64_t wreg[32];
    {
        const float* Up = U + (size_t)(kq * 64) * G4H + gcol;
#pragma unroll
        for (int k4 = 0; k4 < 16; k4++) {
            float w0 = Up[(k4 * 4 + 0) * G4H];
            float w1 = Up[(k4 * 4 + 1) * G4H];
            float w2 = Up[(k4 * 4 + 2) * G4H];
            float w3 = Up[(k4 * 4 + 3) * G4H];
            wreg[k4 * 2 + 0] = pack2(w0, w1);
            wreg[k4 * 2 + 1] = pack2(w2, w3);
        }
    }

    // Zero h double-buffer + partials
    for (int idx = tid; idx < 2 * 2 * HDIM + 1024; idx += REC_THREADS)
        hbuf[idx] = 0.f;
    __syncthreads();

    // Combine-thread state (warps 0/1)
    const bool is_comb = (tid < 64);
    const int  cb  = tid >> 5;          // batch within pair
    const int  cu  = tid & 31;          // unit
    float cst = 0.f;
    float xwr0 = 0.f, xwr1 = 0.f, xwr2 = 0.f, xwr3 = 0.f;
    const size_t xbase = (size_t)(b0 + cb) * T_STEPS * G4H + u0 + cu;
    uint32_t ra_base[CLUSTER_SZ];       // mapa'd peer SMEM bases (combine only)
    if (is_comb) {
        xwr0 = xw[xbase + 0 * HDIM];
        xwr1 = xw[xbase + 1 * HDIM];
        xwr2 = xw[xbase + 2 * HDIM];
        xwr3 = xw[xbase + 3 * HDIM];
#pragma unroll
        for (int r = 0; r < CLUSTER_SZ; r++) {
            asm volatile("mapa.shared::cluster.u32 %0, %1, %2;"
                         : "=r"(ra_base[r]) : "r"(smem_b), "r"(r));
        }
    }

    // mbarriers + zeroed hbuf must be cluster-visible before any peer store.
    CLUSTER_SYNC();

    int ph0 = 0, ph1 = 0;

    for (int t = 0; t < T_STEPS; t++) {
        // Wait for h(t-1): lives in buf[(t+1)&1], signaled on mbar[(t+1)&1]
        if (t > 0) {
            if (t & 1) { MBARRIER_WAIT_PARITY(mbar_b,     ph0); ph0 ^= 1; }
            else       { MBARRIER_WAIT_PARITY(mbar_b + 8, ph1); ph1 ^= 1; }
        }

        const int rd = (t + 1) & 1;
        const uint32_t h0_b = hbuf_b + (uint32_t)(rd * 2 * HDIM + kq * 64) * 4u;
        const uint32_t h1_b = h0_b + HDIM * 4u;

        uint64_t a01 = 0ull, a23 = 0ull, c01 = 0ull, c23 = 0ull;
#pragma unroll
        for (int k4 = 0; k4 < 16; k4++) {
            uint64_t p01, p23, q01, q23;
            lds_v2u64(p01, p23, h0_b + (uint32_t)k4 * 16u);  // broadcast
            lds_v2u64(q01, q23, h1_b + (uint32_t)k4 * 16u);  // broadcast
            a01 = fma_x2(wreg[k4 * 2 + 0], p01, a01);
            a23 = fma_x2(wreg[k4 * 2 + 1], p23, a23);
            c01 = fma_x2(wreg[k4 * 2 + 0], q01, c01);
            c23 = fma_x2(wreg[k4 * 2 + 1], q23, c23);
        }
        float s0, s1, s2, s3, r0, r1, r2, r3;
        unpack2(a01, s0, s1); unpack2(a23, s2, s3);
        unpack2(c01, r0, r1); unpack2(c23, r2, r3);
        float pa = (s0 + s1) + (s2 + s3);
        float pb = (r0 + r1) + (r2 + r3);

        // part[kq][gate][batch][unit] — u consecutive per warp: conflict-free
        part[((kq * 4 + g) * 2 + 0) * 32 + u] = pa;
        part[((kq * 4 + g) * 2 + 1) * 32 + u] = pb;
        __syncthreads();

        if (is_comb) {
            float zi = xwr0, zf = xwr1, zg = xwr2, zo = xwr3;
#pragma unroll
            for (int q = 0; q < 4; q++) {
                zi += part[((q * 4 + 0) * 2 + cb) * 32 + cu];
                zf += part[((q * 4 + 1) * 2 + cb) * 32 + cu];
                zg += part[((q * 4 + 2) * 2 + cb) * 32 + cu];
                zo += part[((q * 4 + 3) * 2 + cb) * 32 + cu];
            }

            float iv = sigmoidf_(zi);
            float fv = sigmoidf_(zf);
            float ov = sigmoidf_(zo);
            cst = fmaf(fv, cst, iv * zg);  // linear candidate activation
            float h = ov * cst;            // linear output activation

            if (STORE_SEQ) {
                out_seq[((size_t)(b0 + cb) * T_STEPS + t) * HDIM + u0 + cu] = h;
            } else if (t == T_STEPS - 1) {
                out_last[(b0 + cb) * HDIM + u0 + cu] = h;
            }

            if (t + 1 < T_STEPS) {
                // R4 signaling: push h(t) slice to all 8 peers' buf[t&1],
                // then arrive on each peer's mbar[t&1] (fire-and-forget).
                const uint32_t hoff = HBUF_OFF * 4u +
                    ((uint32_t)((t & 1) * 2 * HDIM + cb * HDIM + u0 + cu) << 2);
#pragma unroll
                for (int r = 0; r < CLUSTER_SZ; r++) {
                    asm volatile("st.shared::cluster.f32 [%0], %1;"
                                 :: "r"(ra_base[r] + hoff), "f"(h) : "memory");
                }
                const uint32_t moff = MBAR_OFF * 4u + ((uint32_t)(t & 1) << 3);
#pragma unroll
                for (int r = 0; r < CLUSTER_SZ; r++) {
                    asm volatile("mbarrier.arrive.shared::cluster.b64 _, [%0];"
                                 :: "r"(ra_base[r] + moff) : "memory");
                }
            }

            // prefetch next step's xw (after the signal is on the wire)
            if (t + 1 < T_STEPS) {
                const size_t xb = xbase + (size_t)(t + 1) * G4H;
                xwr0 = xw[xb + 0 * HDIM];
                xwr1 = xw[xb + 1 * HDIM];
                xwr2 = xw[xb + 2 * HDIM];
                xwr3 = xw[xb + 3 * HDIM];
            }
        }
        // No end-of-step barrier: next-step part/hbuf writes are ordered
        // behind the mbar wait (which requires this CTA's own arrives).
    }
}

// ---------------------------------------------------------------------------
// Final FC: out[32,1,128] = h1T[32,256] @ Wfc[256,128] + bfc
// ---------------------------------------------------------------------------
__global__ __launch_bounds__(128)
void fc_kernel(const float* __restrict__ h, const float* __restrict__ Wfc,
               const float* __restrict__ bfc, float* __restrict__ out) {
    const int b = blockIdx.x;
    const int j = threadIdx.x;
    const float* hb = h + b * HDIM;
    float acc = bfc[j];
#pragma unroll 16
    for (int k = 0; k < HDIM; k++)
        acc = fmaf(hb[k], Wfc[k * 128 + j], acc);
    out[b * 128 + j] = acc;
}

// ---------------------------------------------------------------------------
// Launch
// ---------------------------------------------------------------------------
#define GEMM_SMEM ((128 * 65 + 128 * 64) * 4)   // 66048
#define REC_SMEM  (REC_FLOATS * 4)              // ~8 KB

extern "C" void kernel_launch(void* const* d_in, const int* in_sizes, int n_in,
                              void* d_out, int out_size) {
    const float* x   = (const float*)d_in[0];
    const float* W0  = (const float*)d_in[1];
    const float* U0  = (const float*)d_in[2];
    const float* b0v = (const float*)d_in[3];
    const float* W1  = (const float*)d_in[4];
    const float* U1  = (const float*)d_in[5];
    const float* b1v = (const float*)d_in[6];
    const float* Wfc = (const float*)d_in[7];
    const float* bfc = (const float*)d_in[8];
    float* out = (float*)d_out;

    float *xw0, *h0seq, *xw1, *h1T;
    cudaGetSymbolAddress((void**)&xw0,   g_xw0);
    cudaGetSymbolAddress((void**)&h0seq, g_h0seq);
    cudaGetSymbolAddress((void**)&xw1,   g_xw1);
    cudaGetSymbolAddress((void**)&h1T,   g_h1T);

    cudaFuncSetAttribute(gemm_xw<128>, cudaFuncAttributeMaxDynamicSharedMemorySize, GEMM_SMEM);
    cudaFuncSetAttribute(gemm_xw<256>, cudaFuncAttributeMaxDynamicSharedMemorySize, GEMM_SMEM);
    cudaFuncSetAttribute(lstm_rec<true>,  cudaFuncAttributeMaxDynamicSharedMemorySize, REC_SMEM);
    cudaFuncSetAttribute(lstm_rec<false>, cudaFuncAttributeMaxDynamicSharedMemorySize, REC_SMEM);

    const long M = (long)NB * T_STEPS;  // 65536 rows

    gemm_xw<128><<<dim3((unsigned)(M / 64), G4H / 64), 256, GEMM_SMEM>>>(x, W0, b0v, xw0);
    lstm_rec<true><<<NB / 2 * CLUSTER_SZ, REC_THREADS, REC_SMEM>>>(xw0, U0, h0seq, nullptr);
    gemm_xw<256><<<dim3((unsigned)(M / 64), G4H / 64), 256, GEMM_SMEM>>>(h0seq, W1, b1v, xw1);
    lstm_rec<false><<<NB / 2 * CLUSTER_SZ, REC_THREADS, REC_SMEM>>>(xw1, U1, nullptr, h1T);
    fc_kernel<<<NB, 128>>>(h1T, Wfc, bfc, out);
}